// round 15
// baseline (speedup 1.0000x reference)
#include <cuda_runtime.h>
#include <cstdint>

#define THREADS 128
#define TB 16
#define MROWS 48
#define LDA 104
#define LDH 260
#define DM 100
#define DIN 72
#define FFD 512
#define NLAYERS 8
#define NCLS 40

#define SX 0
#define SQ 4992
#define SK 9984
#define SV 14976
#define SW0 19968
#define SW1 24096
#define SMEM_FLOATS 28224   // 112,896 B -> 2 CTAs/SM

typedef unsigned long long ull;

__device__ __forceinline__ void ffma2(ull& acc, ull a, ull b) {
  asm("fma.rn.f32x2 %0, %1, %2, %0;" : "+l"(acc) : "l"(a), "l"(b));
}
__device__ __forceinline__ ull pack2(float x, float y) {
  ull r; asm("mov.b64 %0, {%1, %2};" : "=l"(r) : "f"(x), "f"(y)); return r;
}
__device__ __forceinline__ void upk2(ull v, float& lo, float& hi) {
  asm("mov.b64 {%0, %1}, %2;" : "=f"(lo), "=f"(hi) : "l"(v));
}
__device__ __forceinline__ float4 acc_blk(ull lo, ull hi) {
  float4 v; upk2(lo, v.x, v.y); upk2(hi, v.z, v.w); return v;
}
__device__ __forceinline__ uint32_t s2u(const void* p) {
  uint32_t a;
  asm("{.reg .u64 t; cvta.to.shared.u64 t,%1; cvt.u32.u64 %0,t;}" : "=r"(a) : "l"(p));
  return a;
}
__device__ __forceinline__ void cp_async4(uint32_t dst, const float* src, int srcsize) {
  asm volatile("cp.async.ca.shared.global [%0], [%1], 4, %2;"
               :: "r"(dst), "l"(src), "r"(srcsize));
}
#define CP_COMMIT() asm volatile("cp.async.commit_group;")
#define CP_WAIT0()  asm volatile("cp.async.wait_group 0;" ::: "memory")

template <int NA>
__device__ __forceinline__ void zaccn(ull (&acc)[6][NA]) {
#pragma unroll
  for (int r = 0; r < 6; r++)
#pragma unroll
    for (int c = 0; c < NA; c++) acc[r][c] = 0ull;
}

// async-stage transposed weight segment: wt[k][n0+i] = W[i*wstride + kb + k]
// for i<nseg (zero-fill rows i>=nvalid), k<cs. Issue-only; caller commits/waits.
__device__ __forceinline__ void cpa_seg(uint32_t wtb, int span, const float* __restrict__ W,
                                        int wstride, int nvalid, int n0, int nseg,
                                        int kb, int cs) {
  for (int i = threadIdx.x; i < nseg; i += THREADS) {
    bool valid = i < nvalid;
    const float* src = W + (size_t)(valid ? i : 0) * wstride + kb;
    int sz = valid ? 4 : 0;
    uint32_t dst = wtb + (uint32_t)(n0 + i) * 4u;
    for (int j = 0; j < cs; j++)
      cp_async4(dst + (uint32_t)(j * span) * 4u, src + j, sz);
  }
}

// C[m][g] += sum_{k<cs} A[m][k]*Wt[k][g], g = 4tn+64b (b<NB), rows {tm+8r, r<6}.
template <int NB>
__device__ __forceinline__ void gemm_nb(const float* __restrict__ A, int lda,
                                        const float* __restrict__ Wt, int cs,
                                        ull (&acc)[6][2 * NB], int tm, int tn) {
  const float* a0 = A + tm * lda;
  const int SPAN = 64 * NB;
  for (int k = 0; k < cs; k += 4) {
    float4 a[6];
#pragma unroll
    for (int r = 0; r < 6; r++)
      a[r] = *reinterpret_cast<const float4*>(a0 + (8 * r) * lda + k);
#pragma unroll
    for (int kk = 0; kk < 4; kk++) {
      const float* wrow = Wt + (k + kk) * SPAN + 4 * tn;
      float4 w[NB];
#pragma unroll
      for (int b = 0; b < NB; b++)
        w[b] = *reinterpret_cast<const float4*>(wrow + 64 * b);
#pragma unroll
      for (int r = 0; r < 6; r++) {
        float av = (kk == 0) ? a[r].x : (kk == 1) ? a[r].y : (kk == 2) ? a[r].z : a[r].w;
        ull aa = pack2(av, av);
#pragma unroll
        for (int b = 0; b < NB; b++) {
          ffma2(acc[r][2 * b], aa, pack2(w[b].x, w[b].y));
          ffma2(acc[r][2 * b + 1], aa, pack2(w[b].z, w[b].w));
        }
      }
    }
  }
}

// double-buffered pipelined GEMM: wait -> sync -> issue next chunk (async) -> gemm(cur)
template <int NB>
__device__ __forceinline__ void gemm_pipe(const float* A, int lda, float* w0, float* w1,
                                          const float* W, int wstride, int nvalid,
                                          int K, int cs0, ull (&acc)[6][2 * NB],
                                          int tm, int tn) {
  const int span = 64 * NB;
  int cs = K < cs0 ? K : cs0;
  cpa_seg(s2u(w0), span, W, wstride, nvalid, 0, span, 0, cs);
  CP_COMMIT();
  int kb = 0;
  float* cur = w0;
  float* nxt = w1;
  for (;;) {
    int nkb = kb + cs;
    CP_WAIT0();
    __syncthreads();
    int ncs = 0;
    if (nkb < K) {
      ncs = (K - nkb) < cs0 ? (K - nkb) : cs0;
      cpa_seg(s2u(nxt), span, W, wstride, nvalid, 0, span, nkb, ncs);
      CP_COMMIT();
    }
    gemm_nb<NB>(A + kb, lda, cur, cs, acc, tm, tn);
    if (nkb >= K) break;
    float* t = cur; cur = nxt; nxt = t;
    kb = nkb; cs = ncs;
  }
}

__device__ __forceinline__ void epi_qkv(ull (&acc)[6][10], const float* bq_i,
                                        const float* bk_i, const float* bv_i,
                                        float* sQ, float* sK, float* sV, int tm, int tn) {
#pragma unroll
  for (int b = 0; b < 5; b++) {
    int g = 4 * tn + 64 * b;
    int m2 = (g >= 208) ? 2 : (g >= 104 ? 1 : 0);
    int cl = g - 104 * m2;
    if (cl < DM) {
      const float* bias = (m2 == 0) ? bq_i : (m2 == 1) ? bk_i : bv_i;
      float* dst = (m2 == 0) ? sQ : (m2 == 1) ? sK : sV;
      float4 bb = *reinterpret_cast<const float4*>(bias + cl);
#pragma unroll
      for (int r = 0; r < 6; r++) {
        float4 v = acc_blk(acc[r][2 * b], acc[r][2 * b + 1]);
        v.x += bb.x; v.y += bb.y; v.z += bb.z; v.w += bb.w;
        *reinterpret_cast<float4*>(dst + (tm + 8 * r) * LDA + cl) = v;
      }
    }
  }
}

__device__ __forceinline__ void epi_ffn1(ull (&acc)[6][8], const float* b1c,
                                         float* H, int tm, int tn) {
#pragma unroll
  for (int b = 0; b < 4; b++) {
    int g = 4 * tn + 64 * b;
    float4 bb = *reinterpret_cast<const float4*>(b1c + g);
#pragma unroll
    for (int r = 0; r < 6; r++) {
      float4 v = acc_blk(acc[r][2 * b], acc[r][2 * b + 1]);
      v.x = fmaxf(v.x + bb.x, 0.f); v.y = fmaxf(v.y + bb.y, 0.f);
      v.z = fmaxf(v.z + bb.z, 0.f); v.w = fmaxf(v.w + bb.w, 0.f);
      *reinterpret_cast<float4*>(H + (tm + 8 * r) * LDH + g) = v;
    }
  }
}

__device__ __forceinline__ void epi_nb2(ull (&acc)[6][4], const float* bias,
                                        float* dst, const float* resid, int tm, int tn) {
#pragma unroll
  for (int b = 0; b < 2; b++) {
    int g = 4 * tn + 64 * b;
    if (g < DM) {
      float4 bb = *reinterpret_cast<const float4*>(bias + g);
#pragma unroll
      for (int r = 0; r < 6; r++) {
        int row = tm + 8 * r;
        float4 v = acc_blk(acc[r][2 * b], acc[r][2 * b + 1]);
        v.x += bb.x; v.y += bb.y; v.z += bb.z; v.w += bb.w;
        if (resid) {
          float4 rr = *reinterpret_cast<const float4*>(resid + row * LDA + g);
          v.x += rr.x; v.y += rr.y; v.z += rr.z; v.w += rr.w;
        }
        *reinterpret_cast<float4*>(dst + row * LDA + g) = v;
      }
    }
  }
}

__device__ __forceinline__ void layernorm_rows(const float* __restrict__ src,
                                               float* __restrict__ dst,
                                               const float* __restrict__ g,
                                               const float* __restrict__ b) {
  const int tid = threadIdx.x;
  if (tid < MROWS) {
    const float* y = src + tid * LDA;
    float m = 0.f;
#pragma unroll 4
    for (int d = 0; d < DM; d++) m += y[d];
    m *= (1.0f / DM);
    float v = 0.f;
#pragma unroll 4
    for (int d = 0; d < DM; d++) { float t = y[d] - m; v = fmaf(t, t, v); }
    v *= (1.0f / DM);
    float inv = rsqrtf(v + 1e-5f);
    float* o = dst + tid * LDA;
#pragma unroll 4
    for (int d = 0; d < DM; d++)
      o[d] = (y[d] - m) * inv * __ldg(g + d) + __ldg(b + d);
  }
}

__global__ void __launch_bounds__(THREADS, 2)
geomapnet_kernel(const float* __restrict__ x,
                 const float* __restrict__ We, const float* __restrict__ be,
                 const float* __restrict__ pe,
                 const float* __restrict__ Wq, const float* __restrict__ bq,
                 const float* __restrict__ Wk, const float* __restrict__ bk,
                 const float* __restrict__ Wv, const float* __restrict__ bv,
                 const float* __restrict__ Wo, const float* __restrict__ bo,
                 const float* __restrict__ ln1g, const float* __restrict__ ln1b,
                 const float* __restrict__ W1, const float* __restrict__ b1,
                 const float* __restrict__ W2, const float* __restrict__ b2,
                 const float* __restrict__ ln2g, const float* __restrict__ ln2b,
                 const float* __restrict__ Wf, const float* __restrict__ bf,
                 float* __restrict__ out)
{
  extern __shared__ float sm[];
  float* sX = sm + SX;
  float* sQ = sm + SQ;
  float* sK = sm + SK;
  float* sV = sm + SV;
  float* w0 = sm + SW0;
  float* w1 = sm + SW1;
  float* H  = sm + SQ;   // 48 x LDH(260), overlays sQ/sK/sV (dead during FFN)

  const int tid = threadIdx.x;
  const int tn = tid & 15, tm = tid >> 4;
  const int rowbase = blockIdx.x * MROWS;

  // ---- load x -> sQ[48][0..71] ----
  for (int idx = tid; idx < MROWS * (DIN / 4); idx += THREADS) {
    int r = idx / (DIN / 4), c4 = idx - r * (DIN / 4);
    *reinterpret_cast<float4*>(sQ + r * LDA + 4 * c4) =
        *reinterpret_cast<const float4*>(x + (size_t)(rowbase + r) * DIN + 4 * c4);
  }
  __syncthreads();

  // ---- embedding: X = x @ We^T + be + pe ----
  {
    ull a[6][4]; zaccn<4>(a);
    gemm_pipe<2>(sQ, LDA, w0, w1, We, DIN, DM, DIN, 20, a, tm, tn);
#pragma unroll
    for (int b = 0; b < 2; b++) {
      int g = 4 * tn + 64 * b;
      if (g < DM) {
        float4 bb = *reinterpret_cast<const float4*>(be + g);
#pragma unroll
        for (int r = 0; r < 6; r++) {
          int row = tm + 8 * r;
          const float4 pp = *reinterpret_cast<const float4*>(pe + (row % 3) * DM + g);
          float4 v = acc_blk(a[r][2 * b], a[r][2 * b + 1]);
          v.x += bb.x + pp.x; v.y += bb.y + pp.y;
          v.z += bb.z + pp.z; v.w += bb.w + pp.w;
          *reinterpret_cast<float4*>(sX + row * LDA + g) = v;
        }
      }
    }
  }
  __syncthreads();

  // ---- encoder layers ----
  for (int li = 0; li < NLAYERS; li++) {
    const float* Wq_i = Wq + li * DM * DM;
    const float* Wk_i = Wk + li * DM * DM;
    const float* Wv_i = Wv + li * DM * DM;

    // merged QKV: span 320, double-buffered cp.async chunks (cs=12, last 4)
    {
      ull a[6][10]; zaccn<10>(a);
      int cs = 12, kb = 0;
      {
        uint32_t b0 = s2u(w0);
        cpa_seg(b0, 320, Wq_i, DM, DM, 0, 104, 0, cs);
        cpa_seg(b0, 320, Wk_i, DM, DM, 104, 104, 0, cs);
        cpa_seg(b0, 320, Wv_i, DM, DM, 208, 112, 0, cs);
        CP_COMMIT();
      }
      float* cur = w0; float* nxt = w1;
      for (;;) {
        int nkb = kb + cs;
        CP_WAIT0();
        __syncthreads();
        int ncs = 0;
        if (nkb < DM) {
          ncs = (DM - nkb) < 12 ? (DM - nkb) : 12;
          uint32_t bn = s2u(nxt);
          cpa_seg(bn, 320, Wq_i, DM, DM, 0, 104, nkb, ncs);
          cpa_seg(bn, 320, Wk_i, DM, DM, 104, 104, nkb, ncs);
          cpa_seg(bn, 320, Wv_i, DM, DM, 208, 112, nkb, ncs);
          CP_COMMIT();
        }
        gemm_nb<5>(sX + kb, LDA, cur, cs, a, tm, tn);
        if (nkb >= DM) break;
        float* t = cur; cur = nxt; nxt = t;
        kb = nkb; cs = ncs;
      }
      epi_qkv(a, bq + li * DM, bk + li * DM, bv + li * DM, sQ, sK, sV, tm, tn);
    }
    __syncthreads();

    // attention (flat row-major head split), TB*10 = 160 tasks
    for (int task = tid; task < TB * 10; task += THREADS) {
      int e = task / 10, h = task - e * 10;
      const int base = h * 30;
      const float* Qe = sQ + (3 * e) * LDA;
      const float* Ke = sK + (3 * e) * LDA;
      const float* Ve = sV + (3 * e) * LDA;
      auto offf = [&](int f) { int s = f / 100; return s * LDA + (f - s * 100); };
      const float scale = 0.3162277660168379f;
      float att[3][3], q[30];
#pragma unroll
      for (int j = 0; j < 30; j++) q[j] = Qe[offf(base + j)];
#pragma unroll
      for (int b2_ = 0; b2_ < 3; b2_++) {
        float kk[10];
#pragma unroll
        for (int d3 = 0; d3 < 10; d3++) kk[d3] = Ke[offf(base + b2_ * 10 + d3)];
#pragma unroll
        for (int a2 = 0; a2 < 3; a2++) {
          float s2 = 0.f;
#pragma unroll
          for (int d3 = 0; d3 < 10; d3++) s2 = fmaf(q[a2 * 10 + d3], kk[d3], s2);
          att[a2][b2_] = s2 * scale;
        }
      }
#pragma unroll
      for (int a2 = 0; a2 < 3; a2++) {
        float mx = fmaxf(att[a2][0], fmaxf(att[a2][1], att[a2][2]));
        float sum = 0.f;
#pragma unroll
        for (int b2_ = 0; b2_ < 3; b2_++) { att[a2][b2_] = __expf(att[a2][b2_] - mx); sum += att[a2][b2_]; }
        float inv = 1.f / sum;
#pragma unroll
        for (int b2_ = 0; b2_ < 3; b2_++) att[a2][b2_] *= inv;
      }
      float* Qw = sQ + (3 * e) * LDA;
#pragma unroll
      for (int d3 = 0; d3 < 10; d3++) {
        float v0 = Ve[offf(base + d3)], v1 = Ve[offf(base + 10 + d3)], v2 = Ve[offf(base + 20 + d3)];
#pragma unroll
        for (int a2 = 0; a2 < 3; a2++)
          Qw[offf(base + a2 * 10 + d3)] = att[a2][0] * v0 + att[a2][1] * v1 + att[a2][2] * v2;
      }
    }
    __syncthreads();

    // O projection + residual -> sK
    {
      ull a[6][4]; zaccn<4>(a);
      gemm_pipe<2>(sQ, LDA, w0, w1, Wo + li * DM * DM, DM, DM, DM, 20, a, tm, tn);
      epi_nb2(a, bo + li * DM, sK, sX, tm, tn);
    }
    __syncthreads();
    layernorm_rows(sK, sX, ln1g + li * DM, ln1b + li * DM);
    __syncthreads();

    // FFN: 2 supers of 256 hidden; yacc accumulates across all chunks
    {
      ull yacc[6][4]; zaccn<4>(yacc);
      for (int sp = 0; sp < 2; sp++) {
        {
          ull f[6][8]; zaccn<8>(f);
          gemm_pipe<4>(sX, LDA, w0, w1, W1 + (size_t)li * FFD * DM + (size_t)sp * 256 * DM,
                       DM, 256, DM, 16, f, tm, tn);
          epi_ffn1(f, b1 + li * FFD + sp * 256, H, tm, tn);
        }
        __syncthreads();
        gemm_pipe<2>(H, LDH, w0, w1, W2 + (size_t)li * DM * FFD + sp * 256,
                     FFD, DM, 256, 32, yacc, tm, tn);
        __syncthreads();
      }
      epi_nb2(yacc, b2 + li * DM, sK, sX, tm, tn);
    }
    __syncthreads();
    layernorm_rows(sK, sX, ln2g + li * DM, ln2b + li * DM);
    __syncthreads();
  }

  // ---- classifier: out = flat(X)[300] @ Wf^T + bf (Wf from L2) ----
  for (int task = tid; task < TB * NCLS; task += THREADS) {
    int e = task / NCLS, c = task - e * NCLS;
    const float* Xe = sX + 3 * e * LDA;
    const float* wr = Wf + c * 300;
    float dot = __ldg(bf + c);
#pragma unroll
    for (int s = 0; s < 3; s++) {
      const float* xs = Xe + s * LDA;
      const float* ws = wr + s * DM;
#pragma unroll 5
      for (int d = 0; d < DM; d += 4) {
        float4 xv = *reinterpret_cast<const float4*>(xs + d);
        float4 wv = *reinterpret_cast<const float4*>(ws + d);
        dot = fmaf(xv.x, wv.x, dot); dot = fmaf(xv.y, wv.y, dot);
        dot = fmaf(xv.z, wv.z, dot); dot = fmaf(xv.w, wv.w, dot);
      }
    }
    out[(size_t)(blockIdx.x * TB + e) * NCLS + c] = dot;
  }
}

extern "C" void kernel_launch(void* const* d_in, const int* in_sizes, int n_in,
                              void* d_out, int out_size) {
  const float* x   = (const float*)d_in[0];
  const float* We  = (const float*)d_in[3];
  const float* be  = (const float*)d_in[4];
  const float* pe  = (const float*)d_in[5];
  const float* Wq  = (const float*)d_in[6];
  const float* bq  = (const float*)d_in[7];
  const float* Wk  = (const float*)d_in[8];
  const float* bk  = (const float*)d_in[9];
  const float* Wv  = (const float*)d_in[10];
  const float* bv  = (const float*)d_in[11];
  const float* Wo  = (const float*)d_in[12];
  const float* bo  = (const float*)d_in[13];
  const float* l1g = (const float*)d_in[14];
  const float* l1b = (const float*)d_in[15];
  const float* W1  = (const float*)d_in[16];
  const float* b1  = (const float*)d_in[17];
  const float* W2  = (const float*)d_in[18];
  const float* b2  = (const float*)d_in[19];
  const float* l2g = (const float*)d_in[20];
  const float* l2b = (const float*)d_in[21];
  const float* Wf  = (const float*)d_in[22];
  const float* bf  = (const float*)d_in[23];
  float* out = (float*)d_out;

  int Bsz = in_sizes[0] / (3 * DIN);       // 65536
  int nblocks = Bsz / TB;                  // 4096
  size_t smem = (size_t)SMEM_FLOATS * sizeof(float);  // 112,896 B

  cudaFuncSetAttribute(geomapnet_kernel,
                       cudaFuncAttributeMaxDynamicSharedMemorySize, (int)smem);
  geomapnet_kernel<<<nblocks, THREADS, smem>>>(x, We, be, pe, Wq, bq, Wk, bk, Wv, bv,
                                               Wo, bo, l1g, l1b, W1, b1, W2, b2,
                                               l2g, l2b, Wf, bf, out);
}

// round 16
// speedup vs baseline: 1.4866x; 1.4866x over previous
#include <cuda_runtime.h>
#include <cstdint>

#define THREADS 128
#define TB 16
#define MROWS 48
#define LDA 104
#define LDH 260
#define DM 100
#define DIN 72
#define FFD 512
#define NLAYERS 8
#define NCLS 40

#define SX 0
#define SQ 4992
#define SK 9984
#define SV 14976
#define SW0 19968
#define SW1 22528          // second rpipe buffer (2560 floats each)
#define SMEM_FLOATS 27168  // 108,672 B -> 2 CTAs/SM (wt region 7200: QKV 6400 / FFN1 7168)

typedef unsigned long long ull;

__device__ __forceinline__ void ffma2(ull& acc, ull a, ull b) {
  asm("fma.rn.f32x2 %0, %1, %2, %0;" : "+l"(acc) : "l"(a), "l"(b));
}
__device__ __forceinline__ ull pack2(float x, float y) {
  ull r; asm("mov.b64 %0, {%1, %2};" : "=l"(r) : "f"(x), "f"(y)); return r;
}
__device__ __forceinline__ void upk2(ull v, float& lo, float& hi) {
  asm("mov.b64 {%0, %1}, %2;" : "=f"(lo), "=f"(hi) : "l"(v));
}
__device__ __forceinline__ float4 acc_blk(ull lo, ull hi) {
  float4 v; upk2(lo, v.x, v.y); upk2(hi, v.z, v.w); return v;
}

template <int NA>
__device__ __forceinline__ void zaccn(ull (&acc)[6][NA]) {
#pragma unroll
  for (int r = 0; r < 6; r++)
#pragma unroll
    for (int c = 0; c < NA; c++) acc[r][c] = 0ull;
}

// synchronous stage (used by QKV merged + FFN1): wt[k][n0+i] = W[i*ws+kb+k]
__device__ __forceinline__ void stage_seg(float* wt, int span, const float* __restrict__ W,
                                          int wstride, int nvalid, int n0, int nseg,
                                          int kb, int cs) {
  for (int i = threadIdx.x; i < nseg; i += THREADS) {
    const float* src = W + (size_t)i * wstride + kb;
    bool valid = i < nvalid;
    float* dcol = wt + n0 + i;
    for (int j = 0; j < (cs >> 2); j++) {
      float4 v = valid ? *reinterpret_cast<const float4*>(src + 4 * j)
                       : make_float4(0.f, 0.f, 0.f, 0.f);
      float* d = dcol + (4 * j) * span;
      d[0] = v.x; d[span] = v.y; d[2 * span] = v.z; d[3 * span] = v.w;
    }
  }
}

// C[m][g] += sum_{k<cs} A[m][k]*Wt[k][g], g = 4tn+64b (b<NB), rows {tm+8r, r<6}.
template <int NB>
__device__ __forceinline__ void gemm_nb(const float* __restrict__ A, int lda,
                                        const float* __restrict__ Wt, int cs,
                                        ull (&acc)[6][2 * NB], int tm, int tn) {
  const float* a0 = A + tm * lda;
  const int SPAN = 64 * NB;
  for (int k = 0; k < cs; k += 4) {
    float4 a[6];
#pragma unroll
    for (int r = 0; r < 6; r++)
      a[r] = *reinterpret_cast<const float4*>(a0 + (8 * r) * lda + k);
#pragma unroll
    for (int kk = 0; kk < 4; kk++) {
      const float* wrow = Wt + (k + kk) * SPAN + 4 * tn;
      float4 w[NB];
#pragma unroll
      for (int b = 0; b < NB; b++)
        w[b] = *reinterpret_cast<const float4*>(wrow + 64 * b);
#pragma unroll
      for (int r = 0; r < 6; r++) {
        float av = (kk == 0) ? a[r].x : (kk == 1) ? a[r].y : (kk == 2) ? a[r].z : a[r].w;
        ull aa = pack2(av, av);
#pragma unroll
        for (int b = 0; b < NB; b++) {
          ffma2(acc[r][2 * b], aa, pack2(w[b].x, w[b].y));
          ffma2(acc[r][2 * b + 1], aa, pack2(w[b].z, w[b].w));
        }
      }
    }
  }
}

// legacy chunked driver (FFN1): stage -> sync -> gemm -> sync
template <int NB>
__device__ __forceinline__ void gemm_chunks(const float* A, int lda, float* wt,
                                            const float* W, int wstride, int nvalid,
                                            int K, int cs0, ull (&acc)[6][2 * NB],
                                            int tm, int tn) {
  for (int kb = 0; kb < K; ) {
    int cs = K - kb < cs0 ? K - kb : cs0;
    stage_seg(wt, 64 * NB, W, wstride, nvalid, 0, 64 * NB, kb, cs);
    __syncthreads();
    gemm_nb<NB>(A + kb, lda, wt, cs, acc, tm, tn);
    __syncthreads();
    kb += cs;
  }
}

// register-transit double-buffered GEMM (NB=2 only): K must be a multiple of CS.
// Per chunk: ldg(next)->regs ; sync ; gemm(cur) ; sts(regs->next). One sync/chunk.
// Caller MUST __syncthreads() between this and any other wt-region user.
template <int NB, int CS>
__device__ __forceinline__ void gemm_rpipe(const float* A, int lda, float* w0, float* w1,
                                           const float* W, int wstride, int nvalid, int K,
                                           ull (&acc)[6][2 * NB], int tm, int tn) {
  constexpr int SPAN = 64 * NB;           // 128
  constexpr int RPT = SPAN / 128;         // 1
  constexpr int NL = RPT * (CS / 4);
  float4 v[NL];
  const int i0 = threadIdx.x;
  auto ldgc = [&](int kb) {
    int n = 0;
#pragma unroll
    for (int t = 0; t < RPT; t++) {
      int i = i0 + t * 128;
      bool val = i < nvalid;
      const float* s = W + (size_t)(val ? i : 0) * wstride + kb;
#pragma unroll
      for (int j = 0; j < CS / 4; j++) {
        float4 q = *reinterpret_cast<const float4*>(s + 4 * j);
        v[n++] = val ? q : make_float4(0.f, 0.f, 0.f, 0.f);
      }
    }
  };
  auto stsc = [&](float* wt) {
    int n = 0;
#pragma unroll
    for (int t = 0; t < RPT; t++) {
      int i = i0 + t * 128;
#pragma unroll
      for (int j = 0; j < CS / 4; j++) {
        float4 q = v[n++];
        float* d = wt + (4 * j) * SPAN + i;
        d[0] = q.x; d[SPAN] = q.y; d[2 * SPAN] = q.z; d[3 * SPAN] = q.w;
      }
    }
  };
  ldgc(0);
  stsc(w0);
  float* cur = w0; float* nxt = w1;
  for (int kb = 0;;) {
    int nkb = kb + CS;
    if (nkb < K) ldgc(nkb);     // LDG overlaps gemm below
    __syncthreads();
    gemm_nb<NB>(A + kb, lda, cur, CS, acc, tm, tn);
    if (nkb >= K) break;
    stsc(nxt);
    float* t = cur; cur = nxt; nxt = t;
    kb = nkb;
  }
}

__device__ __forceinline__ void epi_qkv(ull (&acc)[6][10], const float* bq_i,
                                        const float* bk_i, const float* bv_i,
                                        float* sQ, float* sK, float* sV, int tm, int tn) {
#pragma unroll
  for (int b = 0; b < 5; b++) {
    int g = 4 * tn + 64 * b;
    int m2 = (g >= 208) ? 2 : (g >= 104 ? 1 : 0);
    int cl = g - 104 * m2;
    if (cl < DM) {
      const float* bias = (m2 == 0) ? bq_i : (m2 == 1) ? bk_i : bv_i;
      float* dst = (m2 == 0) ? sQ : (m2 == 1) ? sK : sV;
      float4 bb = *reinterpret_cast<const float4*>(bias + cl);
#pragma unroll
      for (int r = 0; r < 6; r++) {
        float4 v = acc_blk(acc[r][2 * b], acc[r][2 * b + 1]);
        v.x += bb.x; v.y += bb.y; v.z += bb.z; v.w += bb.w;
        *reinterpret_cast<float4*>(dst + (tm + 8 * r) * LDA + cl) = v;
      }
    }
  }
}

__device__ __forceinline__ void epi_ffn1(ull (&acc)[6][8], const float* b1c,
                                         float* H, int tm, int tn) {
#pragma unroll
  for (int b = 0; b < 4; b++) {
    int g = 4 * tn + 64 * b;
    float4 bb = *reinterpret_cast<const float4*>(b1c + g);
#pragma unroll
    for (int r = 0; r < 6; r++) {
      float4 v = acc_blk(acc[r][2 * b], acc[r][2 * b + 1]);
      v.x = fmaxf(v.x + bb.x, 0.f); v.y = fmaxf(v.y + bb.y, 0.f);
      v.z = fmaxf(v.z + bb.z, 0.f); v.w = fmaxf(v.w + bb.w, 0.f);
      *reinterpret_cast<float4*>(H + (tm + 8 * r) * LDH + g) = v;
    }
  }
}

__device__ __forceinline__ void epi_nb2(ull (&acc)[6][4], const float* bias,
                                        float* dst, const float* resid, int tm, int tn) {
#pragma unroll
  for (int b = 0; b < 2; b++) {
    int g = 4 * tn + 64 * b;
    if (g < DM) {
      float4 bb = *reinterpret_cast<const float4*>(bias + g);
#pragma unroll
      for (int r = 0; r < 6; r++) {
        int row = tm + 8 * r;
        float4 v = acc_blk(acc[r][2 * b], acc[r][2 * b + 1]);
        v.x += bb.x; v.y += bb.y; v.z += bb.z; v.w += bb.w;
        if (resid) {
          float4 rr = *reinterpret_cast<const float4*>(resid + row * LDA + g);
          v.x += rr.x; v.y += rr.y; v.z += rr.z; v.w += rr.w;
        }
        *reinterpret_cast<float4*>(dst + row * LDA + g) = v;
      }
    }
  }
}

__device__ __forceinline__ void layernorm_rows(const float* __restrict__ src,
                                               float* __restrict__ dst,
                                               const float* __restrict__ g,
                                               const float* __restrict__ b) {
  const int tid = threadIdx.x;
  if (tid < MROWS) {
    const float* y = src + tid * LDA;
    float m = 0.f;
#pragma unroll 4
    for (int d = 0; d < DM; d++) m += y[d];
    m *= (1.0f / DM);
    float v = 0.f;
#pragma unroll 4
    for (int d = 0; d < DM; d++) { float t = y[d] - m; v = fmaf(t, t, v); }
    v *= (1.0f / DM);
    float inv = rsqrtf(v + 1e-5f);
    float* o = dst + tid * LDA;
#pragma unroll 4
    for (int d = 0; d < DM; d++)
      o[d] = (y[d] - m) * inv * __ldg(g + d) + __ldg(b + d);
  }
}

__global__ void __launch_bounds__(THREADS, 2)
geomapnet_kernel(const float* __restrict__ x,
                 const float* __restrict__ We, const float* __restrict__ be,
                 const float* __restrict__ pe,
                 const float* __restrict__ Wq, const float* __restrict__ bq,
                 const float* __restrict__ Wk, const float* __restrict__ bk,
                 const float* __restrict__ Wv, const float* __restrict__ bv,
                 const float* __restrict__ Wo, const float* __restrict__ bo,
                 const float* __restrict__ ln1g, const float* __restrict__ ln1b,
                 const float* __restrict__ W1, const float* __restrict__ b1,
                 const float* __restrict__ W2, const float* __restrict__ b2,
                 const float* __restrict__ ln2g, const float* __restrict__ ln2b,
                 const float* __restrict__ Wf, const float* __restrict__ bf,
                 float* __restrict__ out)
{
  extern __shared__ float sm[];
  float* sX = sm + SX;
  float* sQ = sm + SQ;
  float* sK = sm + SK;
  float* sV = sm + SV;
  float* w0 = sm + SW0;
  float* w1 = sm + SW1;
  float* H  = sm + SQ;   // 48 x LDH(260) overlays sQ/sK/sV during FFN

  const int tid = threadIdx.x;
  const int tn = tid & 15, tm = tid >> 4;
  const int rowbase = blockIdx.x * MROWS;

  for (int idx = tid; idx < MROWS * (DIN / 4); idx += THREADS) {
    int r = idx / (DIN / 4), c4 = idx - r * (DIN / 4);
    *reinterpret_cast<float4*>(sQ + r * LDA + 4 * c4) =
        *reinterpret_cast<const float4*>(x + (size_t)(rowbase + r) * DIN + 4 * c4);
  }
  __syncthreads();

  // ---- embedding: X = x @ We^T + be + pe (rpipe, K=72, CS=12) ----
  {
    ull a[6][4]; zaccn<4>(a);
    gemm_rpipe<2, 12>(sQ, LDA, w0, w1, We, DIN, DM, DIN, a, tm, tn);
#pragma unroll
    for (int b = 0; b < 2; b++) {
      int g = 4 * tn + 64 * b;
      if (g < DM) {
        float4 bb = *reinterpret_cast<const float4*>(be + g);
#pragma unroll
        for (int r = 0; r < 6; r++) {
          int row = tm + 8 * r;
          const float4 pp = *reinterpret_cast<const float4*>(pe + (row % 3) * DM + g);
          float4 v = acc_blk(a[r][2 * b], a[r][2 * b + 1]);
          v.x += bb.x + pp.x; v.y += bb.y + pp.y;
          v.z += bb.z + pp.z; v.w += bb.w + pp.w;
          *reinterpret_cast<float4*>(sX + row * LDA + g) = v;
        }
      }
    }
  }
  __syncthreads();

  for (int li = 0; li < NLAYERS; li++) {
    const float* Wq_i = Wq + li * DM * DM;
    const float* Wk_i = Wk + li * DM * DM;
    const float* Wv_i = Wv + li * DM * DM;

    // merged QKV: span 320, 5 chunks of 20 (R12 staging)
    {
      ull a[6][10]; zaccn<10>(a);
      for (int kb = 0; kb < DM; kb += 20) {
        stage_seg(w0, 320, Wq_i, DM, DM, 0, 104, kb, 20);
        stage_seg(w0, 320, Wk_i, DM, DM, 104, 104, kb, 20);
        stage_seg(w0, 320, Wv_i, DM, DM, 208, 112, kb, 20);
        __syncthreads();
        gemm_nb<5>(sX + kb, LDA, w0, 20, a, tm, tn);
        __syncthreads();
      }
      epi_qkv(a, bq + li * DM, bk + li * DM, bv + li * DM, sQ, sK, sV, tm, tn);
    }
    __syncthreads();

    // attention (flat row-major head split), 160 tasks
    for (int task = tid; task < TB * 10; task += THREADS) {
      int e = task / 10, h = task - e * 10;
      const int base = h * 30;
      const float* Qe = sQ + (3 * e) * LDA;
      const float* Ke = sK + (3 * e) * LDA;
      const float* Ve = sV + (3 * e) * LDA;
      auto offf = [&](int f) { int s = f / 100; return s * LDA + (f - s * 100); };
      const float scale = 0.3162277660168379f;
      float att[3][3], q[30];
#pragma unroll
      for (int j = 0; j < 30; j++) q[j] = Qe[offf(base + j)];
#pragma unroll
      for (int b2_ = 0; b2_ < 3; b2_++) {
        float kk[10];
#pragma unroll
        for (int d3 = 0; d3 < 10; d3++) kk[d3] = Ke[offf(base + b2_ * 10 + d3)];
#pragma unroll
        for (int a2 = 0; a2 < 3; a2++) {
          float s2 = 0.f;
#pragma unroll
          for (int d3 = 0; d3 < 10; d3++) s2 = fmaf(q[a2 * 10 + d3], kk[d3], s2);
          att[a2][b2_] = s2 * scale;
        }
      }
#pragma unroll
      for (int a2 = 0; a2 < 3; a2++) {
        float mx = fmaxf(att[a2][0], fmaxf(att[a2][1], att[a2][2]));
        float sum = 0.f;
#pragma unroll
        for (int b2_ = 0; b2_ < 3; b2_++) { att[a2][b2_] = __expf(att[a2][b2_] - mx); sum += att[a2][b2_]; }
        float inv = 1.f / sum;
#pragma unroll
        for (int b2_ = 0; b2_ < 3; b2_++) att[a2][b2_] *= inv;
      }
      float* Qw = sQ + (3 * e) * LDA;
#pragma unroll
      for (int d3 = 0; d3 < 10; d3++) {
        float v0 = Ve[offf(base + d3)], v1 = Ve[offf(base + 10 + d3)], v2 = Ve[offf(base + 20 + d3)];
#pragma unroll
        for (int a2 = 0; a2 < 3; a2++)
          Qw[offf(base + a2 * 10 + d3)] = att[a2][0] * v0 + att[a2][1] * v1 + att[a2][2] * v2;
      }
    }
    __syncthreads();

    // O projection + residual -> sK (rpipe, K=100, CS=20)
    {
      ull a[6][4]; zaccn<4>(a);
      gemm_rpipe<2, 20>(sQ, LDA, w0, w1, Wo + li * DM * DM, DM, DM, DM, a, tm, tn);
      epi_nb2(a, bo + li * DM, sK, sX, tm, tn);
    }
    __syncthreads();
    layernorm_rows(sK, sX, ln1g + li * DM, ln1b + li * DM);
    __syncthreads();

    // FFN: 2 supers of 256 hidden
    {
      ull yacc[6][4]; zaccn<4>(yacc);
      for (int sp = 0; sp < 2; sp++) {
        {
          ull f[6][8]; zaccn<8>(f);
          gemm_chunks<4>(sX, LDA, w0, W1 + (size_t)li * FFD * DM + (size_t)sp * 256 * DM,
                         DM, 256, DM, 28, f, tm, tn);
          epi_ffn1(f, b1 + li * FFD + sp * 256, H, tm, tn);
        }
        __syncthreads();
        // FFN2 accumulate (rpipe, K=256, CS=16)
        gemm_rpipe<2, 16>(H, LDH, w0, w1, W2 + (size_t)li * DM * FFD + sp * 256,
                          FFD, DM, 256, yacc, tm, tn);
        __syncthreads();
      }
      epi_nb2(yacc, b2 + li * DM, sK, sX, tm, tn);
    }
    __syncthreads();
    layernorm_rows(sK, sX, ln2g + li * DM, ln2b + li * DM);
    __syncthreads();
  }

  // ---- classifier ----
  for (int task = tid; task < TB * NCLS; task += THREADS) {
    int e = task / NCLS, c = task - e * NCLS;
    const float* Xe = sX + 3 * e * LDA;
    const float* wr = Wf + c * 300;
    float dot = __ldg(bf + c);
#pragma unroll
    for (int s = 0; s < 3; s++) {
      const float* xs = Xe + s * LDA;
      const float* ws = wr + s * DM;
#pragma unroll 5
      for (int d = 0; d < DM; d += 4) {
        float4 xv = *reinterpret_cast<const float4*>(xs + d);
        float4 wv = *reinterpret_cast<const float4*>(ws + d);
        dot = fmaf(xv.x, wv.x, dot); dot = fmaf(xv.y, wv.y, dot);
        dot = fmaf(xv.z, wv.z, dot); dot = fmaf(xv.w, wv.w, dot);
      }
    }
    out[(size_t)(blockIdx.x * TB + e) * NCLS + c] = dot;
  }
}

extern "C" void kernel_launch(void* const* d_in, const int* in_sizes, int n_in,
                              void* d_out, int out_size) {
  const float* x   = (const float*)d_in[0];
  const float* We  = (const float*)d_in[3];
  const float* be  = (const float*)d_in[4];
  const float* pe  = (const float*)d_in[5];
  const float* Wq  = (const float*)d_in[6];
  const float* bq  = (const float*)d_in[7];
  const float* Wk  = (const float*)d_in[8];
  const float* bk  = (const float*)d_in[9];
  const float* Wv  = (const float*)d_in[10];
  const float* bv  = (const float*)d_in[11];
  const float* Wo  = (const float*)d_in[12];
  const float* bo  = (const float*)d_in[13];
  const float* l1g = (const float*)d_in[14];
  const float* l1b = (const float*)d_in[15];
  const float* W1  = (const float*)d_in[16];
  const float* b1  = (const float*)d_in[17];
  const float* W2  = (const float*)d_in[18];
  const float* b2  = (const float*)d_in[19];
  const float* l2g = (const float*)d_in[20];
  const float* l2b = (const float*)d_in[21];
  const float* Wf  = (const float*)d_in[22];
  const float* bf  = (const float*)d_in[23];
  float* out = (float*)d_out;

  int Bsz = in_sizes[0] / (3 * DIN);       // 65536
  int nblocks = Bsz / TB;                  // 4096
  size_t smem = (size_t)SMEM_FLOATS * sizeof(float);  // 108,672 B

  cudaFuncSetAttribute(geomapnet_kernel,
                       cudaFuncAttributeMaxDynamicSharedMemorySize, (int)smem);
  geomapnet_kernel<<<nblocks, THREADS, smem>>>(x, We, be, pe, Wq, bq, Wk, bk, Wv, bv,
                                               Wo, bo, l1g, l1b, W1, b1, W2, b2,
                                               l2g, l2b, Wf, bf, out);
}